// round 2
// baseline (speedup 1.0000x reference)
#include <cuda_runtime.h>
#include <cstdint>

// Problem sizes (fixed by the reference):
//   x : [4,4096,1024] -> M = 16384, d = 1024, h = 4096
#define M_TOK   16384
#define D_DIM   1024
#define H_DIM   4096

// ---------------- scratch (static device memory; no allocations) -----------
__device__ __align__(16) signed char g_xq [M_TOK * D_DIM];            // 16.7 MB
__device__ __align__(16) signed char g_wq1[H_DIM * D_DIM];            // 4.2 MB
__device__ __align__(16) signed char g_wq2[D_DIM * H_DIM];            // 4.2 MB
__device__ __align__(16) float       g_h  [(size_t)M_TOK * H_DIM];    // 256 MB
__device__ __align__(16) signed char g_hq [(size_t)M_TOK * H_DIM];    // 64 MB
__device__ unsigned g_amax[4];   // 0: x, 1: w1, 2: w2, 3: h (fp32 bits, nonneg)

// ---------------- helpers ---------------------------------------------------
__device__ __forceinline__ unsigned smem_u32(const void* p) {
    return (unsigned)__cvta_generic_to_shared(p);
}
__device__ __forceinline__ void cp16(unsigned dst, const void* src) {
    asm volatile("cp.async.cg.shared.global [%0], [%1], 16;\n" :: "r"(dst), "l"(src));
}
__device__ __forceinline__ void cp_commit() {
    asm volatile("cp.async.commit_group;\n");
}
template <int N>
__device__ __forceinline__ void cp_wait() {
    asm volatile("cp.async.wait_group %0;\n" :: "n"(N));
}

#define MMA_S8(d, a, b)                                                        \
    asm volatile(                                                              \
        "mma.sync.aligned.m16n8k32.row.col.s32.s8.s8.s32 "                     \
        "{%0,%1,%2,%3},{%4,%5,%6,%7},{%8,%9},{%0,%1,%2,%3};"                   \
        : "+r"(d[0]), "+r"(d[1]), "+r"(d[2]), "+r"(d[3])                       \
        : "r"(a[0]), "r"(a[1]), "r"(a[2]), "r"(a[3]), "r"(b[0]), "r"(b[1]))

// ---------------- small kernels --------------------------------------------
__global__ void init_kernel() {
    if (threadIdx.x < 4) g_amax[threadIdx.x] = 0u;
}

__global__ void absmax_kernel(const float4* __restrict__ x, int n4, int slot) {
    float m = 0.f;
    for (int i = blockIdx.x * blockDim.x + threadIdx.x; i < n4;
         i += gridDim.x * blockDim.x) {
        float4 v = x[i];
        m = fmaxf(m, fmaxf(fmaxf(fabsf(v.x), fabsf(v.y)),
                           fmaxf(fabsf(v.z), fabsf(v.w))));
    }
    #pragma unroll
    for (int o = 16; o > 0; o >>= 1)
        m = fmaxf(m, __shfl_xor_sync(0xffffffffu, m, o));
    __shared__ float sm[8];
    if ((threadIdx.x & 31) == 0) sm[threadIdx.x >> 5] = m;
    __syncthreads();
    if (threadIdx.x == 0) {
        float b = sm[0];
        #pragma unroll
        for (int i = 1; i < 8; ++i) b = fmaxf(b, sm[i]);
        atomicMax(&g_amax[slot], __float_as_uint(b));
    }
}

__device__ __forceinline__ signed char quant1(float v, float scale) {
    float r = fminf(fmaxf(rintf(v / scale), -127.f), 127.f);
    return (signed char)(int)r;
}

__global__ void quant_kernel(const float4* __restrict__ x, char4* __restrict__ q,
                             int n4, int slot) {
    float scale = fmaxf(__uint_as_float(g_amax[slot]), 1e-8f) / 127.f;
    int i = blockIdx.x * blockDim.x + threadIdx.x;
    if (i < n4) {
        float4 v = x[i];
        char4 o;
        o.x = quant1(v.x, scale);
        o.y = quant1(v.y, scale);
        o.z = quant1(v.z, scale);
        o.w = quant1(v.w, scale);
        q[i] = o;
    }
}

// ---------------- int8 GEMM -------------------------------------------------
// C[M,N] = A[M,K](s8, row-major) * B[N,K](s8, row-major, used as col-major op)
// BM=128, BN=128, BK=64, 256 threads, 8 warps (2 x 4), warp tile 64x32.
// EPI 0: v = acc*s + bias; gelu; store fp32 to Cout; track absmax -> g_amax[3]
// EPI 1: v = acc*s + bias; store fp32 to Cout
template <int EPI>
__global__ __launch_bounds__(256, 2)
void gemm_s8_kernel(const signed char* __restrict__ A,
                    const signed char* __restrict__ B,
                    const float* __restrict__ bias,
                    float* __restrict__ Cout,
                    int K, int N, int saslot, int sbslot) {
    __shared__ signed char sA[2][128][80];
    __shared__ signed char sB[2][128][80];

    const int tid  = threadIdx.x;
    const int lane = tid & 31;
    const int warp = tid >> 5;
    const int wm = (warp >> 2) * 64;   // warp row base in tile (0 / 64)
    const int wn = (warp & 3) * 32;    // warp col base in tile (0..96)

    const int rowA0 = blockIdx.y * 128;
    const int colB0 = blockIdx.x * 128;

    int acc[4][4][4];
    #pragma unroll
    for (int i = 0; i < 4; ++i)
        #pragma unroll
        for (int j = 0; j < 4; ++j)
            #pragma unroll
            for (int r = 0; r < 4; ++r) acc[i][j][r] = 0;

    const int KT = K >> 6;  // K / 64

    // stage loader: 512 16B chunks per matrix; 256 threads x 2
    auto load_stage = [&](int st, int kt) {
        const int k0 = kt << 6;
        #pragma unroll
        for (int c = 0; c < 2; ++c) {
            int chunk = tid + c * 256;
            int row  = chunk >> 2;
            int c16  = (chunk & 3) << 4;
            cp16(smem_u32(&sA[st][row][c16]),
                 A + (size_t)(rowA0 + row) * K + k0 + c16);
            cp16(smem_u32(&sB[st][row][c16]),
                 B + (size_t)(colB0 + row) * K + k0 + c16);
        }
        cp_commit();
    };

    load_stage(0, 0);

    for (int kt = 0; kt < KT; ++kt) {
        const int buf = kt & 1;
        if (kt + 1 < KT) {
            load_stage(buf ^ 1, kt + 1);
            cp_wait<1>();
        } else {
            cp_wait<0>();
        }
        __syncthreads();

        #pragma unroll
        for (int ks = 0; ks < 2; ++ks) {
            const int kc = ks * 32 + (lane & 3) * 4;
            const int r0 = lane >> 2;
            unsigned a[4][4], b[4][2];
            #pragma unroll
            for (int i = 0; i < 4; ++i) {
                const signed char* pa = &sA[buf][wm + i * 16 + r0][kc];
                a[i][0] = *(const unsigned*)(pa);
                a[i][1] = *(const unsigned*)(pa + 8 * 80);
                a[i][2] = *(const unsigned*)(pa + 16);
                a[i][3] = *(const unsigned*)(pa + 8 * 80 + 16);
            }
            #pragma unroll
            for (int j = 0; j < 4; ++j) {
                const signed char* pb = &sB[buf][wn + j * 8 + r0][kc];
                b[j][0] = *(const unsigned*)(pb);
                b[j][1] = *(const unsigned*)(pb + 16);
            }
            #pragma unroll
            for (int i = 0; i < 4; ++i)
                #pragma unroll
                for (int j = 0; j < 4; ++j)
                    MMA_S8(acc[i][j], a[i], b[j]);
        }
        __syncthreads();
    }

    // epilogue
    const float sa = fmaxf(__uint_as_float(g_amax[saslot]), 1e-8f) / 127.f;
    const float sb = fmaxf(__uint_as_float(g_amax[sbslot]), 1e-8f) / 127.f;
    const float s  = sa * sb;

    float lmax = 0.f;
    #pragma unroll
    for (int i = 0; i < 4; ++i) {
        #pragma unroll
        for (int j = 0; j < 4; ++j) {
            const int row0 = rowA0 + wm + i * 16 + (lane >> 2);
            const int col0 = colB0 + wn + j * 8 + (lane & 3) * 2;
            #pragma unroll
            for (int rr = 0; rr < 2; ++rr) {
                const int row = row0 + rr * 8;
                #pragma unroll
                for (int cc = 0; cc < 2; ++cc) {
                    const int col = col0 + cc;
                    float v = fmaf((float)acc[i][j][rr * 2 + cc], s, bias[col]);
                    if (EPI == 0) {
                        float g = 0.5f * v * (1.f + erff(v * 0.70710678118654752f));
                        Cout[(size_t)row * N + col] = g;
                        lmax = fmaxf(lmax, fabsf(g));
                    } else {
                        Cout[(size_t)row * N + col] = v;
                    }
                }
            }
        }
    }
    if (EPI == 0) {
        #pragma unroll
        for (int o = 16; o > 0; o >>= 1)
            lmax = fmaxf(lmax, __shfl_xor_sync(0xffffffffu, lmax, o));
        if (lane == 0) atomicMax(&g_amax[3], __float_as_uint(lmax));
    }
}

// ---------------- launch ----------------------------------------------------
extern "C" void kernel_launch(void* const* d_in, const int* in_sizes, int n_in,
                              void* d_out, int out_size) {
    const float* x  = (const float*)d_in[0];
    const float* w1 = (const float*)d_in[1];
    const float* b1 = (const float*)d_in[2];
    const float* w2 = (const float*)d_in[3];
    const float* b2 = (const float*)d_in[4];
    float* out = (float*)d_out;

    signed char *xq, *wq1, *wq2, *hq;
    float* hbuf;
    cudaGetSymbolAddress((void**)&xq,   g_xq);
    cudaGetSymbolAddress((void**)&wq1,  g_wq1);
    cudaGetSymbolAddress((void**)&wq2,  g_wq2);
    cudaGetSymbolAddress((void**)&hbuf, g_h);
    cudaGetSymbolAddress((void**)&hq,   g_hq);

    const int nx  = M_TOK * D_DIM;      // 16.7M
    const int nw1 = H_DIM * D_DIM;      // 4.2M
    const int nw2 = D_DIM * H_DIM;      // 4.2M
    const int nh  = M_TOK;              // rows; nh*H_DIM elements

    init_kernel<<<1, 32>>>();

    absmax_kernel<<<1024, 256>>>((const float4*)x,  nx  / 4, 0);
    absmax_kernel<<<512,  256>>>((const float4*)w1, nw1 / 4, 1);
    absmax_kernel<<<512,  256>>>((const float4*)w2, nw2 / 4, 2);

    quant_kernel<<<(nx  / 4) / 256, 256>>>((const float4*)x,  (char4*)xq,  nx  / 4, 0);
    quant_kernel<<<(nw1 / 4) / 256, 256>>>((const float4*)w1, (char4*)wq1, nw1 / 4, 1);
    quant_kernel<<<(nw2 / 4) / 256, 256>>>((const float4*)w2, (char4*)wq2, nw2 / 4, 2);

    // GEMM1: [16384,1024] x [4096,1024]^T -> h fp32 (gelu) + absmax(h)
    {
        dim3 grid(H_DIM / 128, M_TOK / 128);
        gemm_s8_kernel<0><<<grid, 256>>>(xq, wq1, b1, hbuf, D_DIM, H_DIM, 0, 1);
    }

    // quantize h
    {
        size_t n4 = ((size_t)nh * H_DIM) / 4;   // 16.7M float4
        quant_kernel<<<(unsigned)(n4 / 256), 256>>>((const float4*)hbuf, (char4*)hq,
                                                    (int)n4, 3);
    }

    // GEMM2: [16384,4096] x [1024,4096]^T -> out
    {
        dim3 grid(D_DIM / 128, M_TOK / 128);
        gemm_s8_kernel<1><<<grid, 256>>>(hq, wq2, b2, out, H_DIM, D_DIM, 3, 2);
    }
    (void)in_sizes; (void)n_in; (void)out_size;
}

// round 4
// speedup vs baseline: 1.0318x; 1.0318x over previous
#include <cuda_runtime.h>
#include <cstdint>

// Problem sizes (fixed by the reference):
//   x : [4,4096,1024] -> M = 16384, d = 1024, h = 4096
#define M_TOK   16384
#define D_DIM   1024
#define H_DIM   4096

// ---------------- scratch (static device memory; no allocations) -----------
__device__ __align__(16) signed char g_xq [M_TOK * D_DIM];            // 16.7 MB
__device__ __align__(16) signed char g_wq1[H_DIM * D_DIM];            // 4.2 MB
__device__ __align__(16) signed char g_wq2[D_DIM * H_DIM];            // 4.2 MB
__device__ __align__(16) float       g_h  [(size_t)M_TOK * H_DIM];    // 256 MB
__device__ __align__(16) signed char g_hq [(size_t)M_TOK * H_DIM];    // 64 MB
__device__ unsigned g_amax[4];   // 0: x, 1: w1, 2: w2, 3: h (fp32 bits, nonneg)

// ---------------- helpers ---------------------------------------------------
__device__ __forceinline__ unsigned smem_u32(const void* p) {
    return (unsigned)__cvta_generic_to_shared(p);
}
__device__ __forceinline__ void cp16(unsigned dst, const void* src) {
    asm volatile("cp.async.cg.shared.global [%0], [%1], 16;\n" :: "r"(dst), "l"(src));
}
__device__ __forceinline__ void cp_commit() {
    asm volatile("cp.async.commit_group;\n");
}
template <int N>
__device__ __forceinline__ void cp_wait() {
    asm volatile("cp.async.wait_group %0;\n" :: "n"(N));
}
__device__ __forceinline__ void ldsm4(unsigned& r0, unsigned& r1, unsigned& r2,
                                      unsigned& r3, unsigned addr) {
    asm volatile("ldmatrix.sync.aligned.m8n8.x4.shared.b16 {%0,%1,%2,%3}, [%4];"
                 : "=r"(r0), "=r"(r1), "=r"(r2), "=r"(r3) : "r"(addr));
}

#define MMA_S8(d, a, b)                                                        \
    asm volatile(                                                              \
        "mma.sync.aligned.m16n8k32.row.col.s32.s8.s8.s32 "                     \
        "{%0,%1,%2,%3},{%4,%5,%6,%7},{%8,%9},{%0,%1,%2,%3};"                   \
        : "+r"(d[0]), "+r"(d[1]), "+r"(d[2]), "+r"(d[3])                       \
        : "r"(a[0]), "r"(a[1]), "r"(a[2]), "r"(a[3]), "r"(b[0]), "r"(b[1]))

// ---------------- small kernels --------------------------------------------
__global__ void init_kernel() {
    if (threadIdx.x < 4) g_amax[threadIdx.x] = 0u;
}

__global__ void absmax_kernel(const float4* __restrict__ x, int n4, int slot) {
    float m = 0.f;
    for (int i = blockIdx.x * blockDim.x + threadIdx.x; i < n4;
         i += gridDim.x * blockDim.x) {
        float4 v = x[i];
        m = fmaxf(m, fmaxf(fmaxf(fabsf(v.x), fabsf(v.y)),
                           fmaxf(fabsf(v.z), fabsf(v.w))));
    }
    #pragma unroll
    for (int o = 16; o > 0; o >>= 1)
        m = fmaxf(m, __shfl_xor_sync(0xffffffffu, m, o));
    __shared__ float sm[8];
    if ((threadIdx.x & 31) == 0) sm[threadIdx.x >> 5] = m;
    __syncthreads();
    if (threadIdx.x == 0) {
        float b = sm[0];
        #pragma unroll
        for (int i = 1; i < 8; ++i) b = fmaxf(b, sm[i]);
        atomicMax(&g_amax[slot], __float_as_uint(b));
    }
}

__device__ __forceinline__ signed char quant1(float v, float scale) {
    float r = fminf(fmaxf(rintf(v / scale), -127.f), 127.f);
    return (signed char)(int)r;
}

__global__ void quant_kernel(const float4* __restrict__ x, char4* __restrict__ q,
                             int n4, int slot) {
    float scale = fmaxf(__uint_as_float(g_amax[slot]), 1e-8f) / 127.f;
    int i = blockIdx.x * blockDim.x + threadIdx.x;
    if (i < n4) {
        float4 v = x[i];
        char4 o;
        o.x = quant1(v.x, scale);
        o.y = quant1(v.y, scale);
        o.z = quant1(v.z, scale);
        o.w = quant1(v.w, scale);
        q[i] = o;
    }
}

// ---------------- int8 GEMM (mma.sync + ldmatrix) ---------------------------
// C[M,N] = A[M,K](s8, row-major) * B[N,K](s8, row-major, used as col-major op)
// BM=128, BN=128, BK=64, 256 threads, 8 warps (2 x 4), warp tile 64x32.
// EPI 0: v = acc*s + bias; gelu; store fp32 to Cout; track absmax -> g_amax[3]
// EPI 1: v = acc*s + bias; store fp32 to Cout
template <int EPI>
__global__ __launch_bounds__(256, 2)
void gemm_s8_kernel(const signed char* __restrict__ A,
                    const signed char* __restrict__ B,
                    const float* __restrict__ bias,
                    float* __restrict__ Cout,
                    int K, int N, int saslot, int sbslot) {
    __shared__ signed char sA[2][128][80];
    __shared__ signed char sB[2][128][80];

    const int tid  = threadIdx.x;
    const int lane = tid & 31;
    const int warp = tid >> 5;
    const int wm = (warp >> 2) * 64;   // warp row base in tile (0 / 64)
    const int wn = (warp & 3) * 32;    // warp col base in tile (0..96)

    const int rowA0 = blockIdx.y * 128;
    const int colB0 = blockIdx.x * 128;

    int acc[4][4][4];
    #pragma unroll
    for (int i = 0; i < 4; ++i)
        #pragma unroll
        for (int j = 0; j < 4; ++j)
            #pragma unroll
            for (int r = 0; r < 4; ++r) acc[i][j][r] = 0;

    const int KT = K >> 6;  // K / 64

    // stage loader: 512 16B chunks per matrix; 256 threads x 2
    auto load_stage = [&](int st, int kt) {
        const int k0 = kt << 6;
        #pragma unroll
        for (int c = 0; c < 2; ++c) {
            int chunk = tid + c * 256;
            int row  = chunk >> 2;
            int c16  = (chunk & 3) << 4;
            cp16(smem_u32(&sA[st][row][c16]),
                 A + (size_t)(rowA0 + row) * K + k0 + c16);
            cp16(smem_u32(&sB[st][row][c16]),
                 B + (size_t)(colB0 + row) * K + k0 + c16);
        }
        cp_commit();
    };

    load_stage(0, 0);

    // ldmatrix per-lane source offsets (within the warp's 64x- / 32x- block)
    const int sub = lane >> 3;           // which 8x16B matrix this lane feeds
    // A tile i: rows (lane&7) + (sub&1)*8, cols (sub>>1)*16  (+ ks*32)
    const int a_row = (lane & 7) + ((sub & 1) << 3);
    const int a_col = (sub >> 1) << 4;
    // B pair j2: rows (lane&7) + (sub>>1)*8, cols (sub&1)*16 (+ ks*32)
    const int b_row = (lane & 7) + ((sub >> 1) << 3);
    const int b_col = (sub & 1) << 4;

    for (int kt = 0; kt < KT; ++kt) {
        const int buf = kt & 1;
        if (kt + 1 < KT) {
            load_stage(buf ^ 1, kt + 1);
            cp_wait<1>();
        } else {
            cp_wait<0>();
        }
        __syncthreads();

        #pragma unroll
        for (int ks = 0; ks < 2; ++ks) {
            unsigned a[4][4], b[4][2];
            #pragma unroll
            for (int i = 0; i < 4; ++i) {
                unsigned addr = smem_u32(
                    &sA[buf][wm + i * 16 + a_row][ks * 32 + a_col]);
                ldsm4(a[i][0], a[i][1], a[i][2], a[i][3], addr);
            }
            #pragma unroll
            for (int j2 = 0; j2 < 2; ++j2) {
                unsigned addr = smem_u32(
                    &sB[buf][wn + j2 * 16 + b_row][ks * 32 + b_col]);
                // regs: {b[2*j2][0], b[2*j2][1], b[2*j2+1][0], b[2*j2+1][1]}
                ldsm4(b[2 * j2][0], b[2 * j2][1],
                      b[2 * j2 + 1][0], b[2 * j2 + 1][1], addr);
            }
            #pragma unroll
            for (int i = 0; i < 4; ++i)
                #pragma unroll
                for (int j = 0; j < 4; ++j)
                    MMA_S8(acc[i][j], a[i], b[j]);
        }
        __syncthreads();
    }

    // epilogue
    const float sa = fmaxf(__uint_as_float(g_amax[saslot]), 1e-8f) / 127.f;
    const float sb = fmaxf(__uint_as_float(g_amax[sbslot]), 1e-8f) / 127.f;
    const float s  = sa * sb;

    float lmax = 0.f;
    #pragma unroll
    for (int i = 0; i < 4; ++i) {
        #pragma unroll
        for (int j = 0; j < 4; ++j) {
            const int row0 = rowA0 + wm + i * 16 + (lane >> 2);
            const int col0 = colB0 + wn + j * 8 + (lane & 3) * 2;
            #pragma unroll
            for (int rr = 0; rr < 2; ++rr) {
                const int row = row0 + rr * 8;
                float2 v;
                float t0 = fmaf((float)acc[i][j][rr * 2 + 0], s, bias[col0 + 0]);
                float t1 = fmaf((float)acc[i][j][rr * 2 + 1], s, bias[col0 + 1]);
                if (EPI == 0) {
                    t0 = 0.5f * t0 * (1.f + erff(t0 * 0.70710678118654752f));
                    t1 = 0.5f * t1 * (1.f + erff(t1 * 0.70710678118654752f));
                    lmax = fmaxf(lmax, fmaxf(fabsf(t0), fabsf(t1)));
                }
                v.x = t0; v.y = t1;
                *(float2*)(Cout + (size_t)row * N + col0) = v;
            }
        }
    }
    if (EPI == 0) {
        #pragma unroll
        for (int o = 16; o > 0; o >>= 1)
            lmax = fmaxf(lmax, __shfl_xor_sync(0xffffffffu, lmax, o));
        if (lane == 0) atomicMax(&g_amax[3], __float_as_uint(lmax));
    }
}

// ---------------- launch ----------------------------------------------------
extern "C" void kernel_launch(void* const* d_in, const int* in_sizes, int n_in,
                              void* d_out, int out_size) {
    const float* x  = (const float*)d_in[0];
    const float* w1 = (const float*)d_in[1];
    const float* b1 = (const float*)d_in[2];
    const float* w2 = (const float*)d_in[3];
    const float* b2 = (const float*)d_in[4];
    float* out = (float*)d_out;

    signed char *xq, *wq1, *wq2, *hq;
    float* hbuf;
    cudaGetSymbolAddress((void**)&xq,   g_xq);
    cudaGetSymbolAddress((void**)&wq1,  g_wq1);
    cudaGetSymbolAddress((void**)&wq2,  g_wq2);
    cudaGetSymbolAddress((void**)&hbuf, g_h);
    cudaGetSymbolAddress((void**)&hq,   g_hq);

    const int nx  = M_TOK * D_DIM;      // 16.7M
    const int nw1 = H_DIM * D_DIM;      // 4.2M
    const int nw2 = D_DIM * H_DIM;      // 4.2M

    init_kernel<<<1, 32>>>();

    absmax_kernel<<<1024, 256>>>((const float4*)x,  nx  / 4, 0);
    absmax_kernel<<<512,  256>>>((const float4*)w1, nw1 / 4, 1);
    absmax_kernel<<<512,  256>>>((const float4*)w2, nw2 / 4, 2);

    quant_kernel<<<(nx  / 4) / 256, 256>>>((const float4*)x,  (char4*)xq,  nx  / 4, 0);
    quant_kernel<<<(nw1 / 4) / 256, 256>>>((const float4*)w1, (char4*)wq1, nw1 / 4, 1);
    quant_kernel<<<(nw2 / 4) / 256, 256>>>((const float4*)w2, (char4*)wq2, nw2 / 4, 2);

    // GEMM1: [16384,1024] x [4096,1024]^T -> h fp32 (gelu) + absmax(h)
    {
        dim3 grid(H_DIM / 128, M_TOK / 128);
        gemm_s8_kernel<0><<<grid, 256>>>(xq, wq1, b1, hbuf, D_DIM, H_DIM, 0, 1);
    }

    // quantize h
    {
        size_t n4 = ((size_t)M_TOK * H_DIM) / 4;   // 16.7M float4
        quant_kernel<<<(unsigned)(n4 / 256), 256>>>((const float4*)hbuf, (char4*)hq,
                                                    (int)n4, 3);
    }

    // GEMM2: [16384,4096] x [1024,4096]^T -> out
    {
        dim3 grid(D_DIM / 128, M_TOK / 128);
        gemm_s8_kernel<1><<<grid, 256>>>(hq, wq2, b2, out, H_DIM, D_DIM, 3, 2);
    }
    (void)in_sizes; (void)n_in; (void)out_size;
}

// round 5
// speedup vs baseline: 1.2489x; 1.2104x over previous
#include <cuda_runtime.h>
#include <cuda_bf16.h>
#include <cstdint>

#define M_TOK   16384
#define D_DIM   1024
#define H_DIM   4096

// ---------------- scratch (static device memory; no allocations) -----------
__device__ __align__(16) __nv_bfloat16 g_xb [M_TOK * D_DIM];          // 33.5 MB
__device__ __align__(16) __nv_bfloat16 g_w1b[H_DIM * D_DIM];          // 8.4 MB
__device__ __align__(16) signed char   g_wq2[D_DIM * H_DIM];          // 4.2 MB
__device__ __align__(16) float         g_h  [(size_t)M_TOK * H_DIM];  // 256 MB
__device__ __align__(16) signed char   g_hq [(size_t)M_TOK * H_DIM];  // 64 MB
__device__ unsigned g_amax[4];   // 0: x, 1: w1, 2: w2, 3: h (fp32 bits)

// ---------------- helpers ---------------------------------------------------
__device__ __forceinline__ unsigned smem_u32(const void* p) {
    return (unsigned)__cvta_generic_to_shared(p);
}
__device__ __forceinline__ void cp16(unsigned dst, const void* src) {
    asm volatile("cp.async.cg.shared.global [%0], [%1], 16;\n" :: "r"(dst), "l"(src));
}
__device__ __forceinline__ void cp_commit() {
    asm volatile("cp.async.commit_group;\n");
}
template <int N>
__device__ __forceinline__ void cp_wait() {
    asm volatile("cp.async.wait_group %0;\n" :: "n"(N));
}
__device__ __forceinline__ void ldsm4(unsigned& r0, unsigned& r1, unsigned& r2,
                                      unsigned& r3, unsigned addr) {
    asm volatile("ldmatrix.sync.aligned.m8n8.x4.shared.b16 {%0,%1,%2,%3}, [%4];"
                 : "=r"(r0), "=r"(r1), "=r"(r2), "=r"(r3) : "r"(addr));
}

#define MMA_S8(d, a, b)                                                        \
    asm volatile(                                                              \
        "mma.sync.aligned.m16n8k32.row.col.s32.s8.s8.s32 "                     \
        "{%0,%1,%2,%3},{%4,%5,%6,%7},{%8,%9},{%0,%1,%2,%3};"                   \
        : "+r"(d[0]), "+r"(d[1]), "+r"(d[2]), "+r"(d[3])                       \
        : "r"(a[0]), "r"(a[1]), "r"(a[2]), "r"(a[3]), "r"(b[0]), "r"(b[1]))

#define MMA_BF16(d, a, b)                                                      \
    asm volatile(                                                              \
        "mma.sync.aligned.m16n8k16.row.col.f32.bf16.bf16.f32 "                 \
        "{%0,%1,%2,%3},{%4,%5,%6,%7},{%8,%9},{%0,%1,%2,%3};"                   \
        : "+f"(d[0]), "+f"(d[1]), "+f"(d[2]), "+f"(d[3])                       \
        : "r"(a[0]), "r"(a[1]), "r"(a[2]), "r"(a[3]), "r"(b[0]), "r"(b[1]))

// ---------------- fused prep kernels ----------------------------------------
__global__ void init_kernel() {
    if (threadIdx.x < 4) g_amax[threadIdx.x] = 0u;
}

// blocks [0,1024): x | [1024,1280): w1 | [1280,1536): w2
__global__ void absmax_all_kernel(const float4* __restrict__ x,
                                  const float4* __restrict__ w1,
                                  const float4* __restrict__ w2) {
    const float4* p;
    int n4, slot, lb, nb;
    int b = blockIdx.x;
    if (b < 1024)      { p = x;  n4 = (M_TOK * D_DIM) / 4; slot = 0; lb = b;        nb = 1024; }
    else if (b < 1280) { p = w1; n4 = (H_DIM * D_DIM) / 4; slot = 1; lb = b - 1024; nb = 256; }
    else               { p = w2; n4 = (D_DIM * H_DIM) / 4; slot = 2; lb = b - 1280; nb = 256; }

    float m = 0.f;
    for (int i = lb * blockDim.x + threadIdx.x; i < n4; i += nb * blockDim.x) {
        float4 v = p[i];
        m = fmaxf(m, fmaxf(fmaxf(fabsf(v.x), fabsf(v.y)),
                           fmaxf(fabsf(v.z), fabsf(v.w))));
    }
    #pragma unroll
    for (int o = 16; o > 0; o >>= 1)
        m = fmaxf(m, __shfl_xor_sync(0xffffffffu, m, o));
    __shared__ float sm[8];
    if ((threadIdx.x & 31) == 0) sm[threadIdx.x >> 5] = m;
    __syncthreads();
    if (threadIdx.x == 0) {
        float v = sm[0];
        #pragma unroll
        for (int i = 1; i < 8; ++i) v = fmaxf(v, sm[i]);
        atomicMax(&g_amax[slot], __float_as_uint(v));
    }
}

__device__ __forceinline__ float quantf(float v, float scale) {
    return fminf(fmaxf(rintf(v / scale), -127.f), 127.f);
}
__device__ __forceinline__ unsigned short bf16bits(float v) {
    __nv_bfloat16 h = __float2bfloat16(v);
    return *(unsigned short*)&h;
}

// blocks [0,16384): x -> bf16 | [16384,20480): w1 -> bf16 | [20480,24576): w2 -> s8
__global__ void quant_all_kernel(const float4* __restrict__ x,
                                 const float4* __restrict__ w1,
                                 const float4* __restrict__ w2) {
    int b = blockIdx.x;
    if (b < 16384) {
        float scale = fmaxf(__uint_as_float(g_amax[0]), 1e-8f) / 127.f;
        int i = b * blockDim.x + threadIdx.x;
        float4 v = x[i];
        ushort4 o;
        o.x = bf16bits(quantf(v.x, scale));
        o.y = bf16bits(quantf(v.y, scale));
        o.z = bf16bits(quantf(v.z, scale));
        o.w = bf16bits(quantf(v.w, scale));
        ((ushort4*)g_xb)[i] = o;
    } else if (b < 20480) {
        float scale = fmaxf(__uint_as_float(g_amax[1]), 1e-8f) / 127.f;
        int i = (b - 16384) * blockDim.x + threadIdx.x;
        float4 v = w1[i];
        ushort4 o;
        o.x = bf16bits(quantf(v.x, scale));
        o.y = bf16bits(quantf(v.y, scale));
        o.z = bf16bits(quantf(v.z, scale));
        o.w = bf16bits(quantf(v.w, scale));
        ((ushort4*)g_w1b)[i] = o;
    } else {
        float scale = fmaxf(__uint_as_float(g_amax[2]), 1e-8f) / 127.f;
        int i = (b - 20480) * blockDim.x + threadIdx.x;
        float4 v = w2[i];
        char4 o;
        o.x = (signed char)(int)quantf(v.x, scale);
        o.y = (signed char)(int)quantf(v.y, scale);
        o.z = (signed char)(int)quantf(v.z, scale);
        o.w = (signed char)(int)quantf(v.w, scale);
        ((char4*)g_wq2)[i] = o;
    }
}

__global__ void quant_h_kernel(const float4* __restrict__ x, char4* __restrict__ q,
                               int n4) {
    float scale = fmaxf(__uint_as_float(g_amax[3]), 1e-8f) / 127.f;
    int i = blockIdx.x * blockDim.x + threadIdx.x;
    if (i < n4) {
        float4 v = x[i];
        char4 o;
        o.x = (signed char)(int)quantf(v.x, scale);
        o.y = (signed char)(int)quantf(v.y, scale);
        o.z = (signed char)(int)quantf(v.z, scale);
        o.w = (signed char)(int)quantf(v.w, scale);
        q[i] = o;
    }
}

// ---------------- bf16 GEMM1 (mma.sync m16n8k16 + ldmatrix) ------------------
// C[M,N] = A[M,K](bf16 row-major) * B[N,K](bf16 row-major as col-major op)
// BM=128, BN=128, BK=32 elements (64B), 256 threads, 8 warps, warp 64x32.
// Epilogue: v = acc*s + bias; exact gelu; store fp32; absmax -> g_amax[3]
__global__ __launch_bounds__(256, 2)
void gemm_bf16_kernel(const __nv_bfloat16* __restrict__ A,
                      const __nv_bfloat16* __restrict__ B,
                      const float* __restrict__ bias,
                      float* __restrict__ Cout,
                      int K, int N) {
    __shared__ signed char sA[2][128][80];   // 32 bf16 = 64B data + 16B pad
    __shared__ signed char sB[2][128][80];

    const int tid  = threadIdx.x;
    const int lane = tid & 31;
    const int warp = tid >> 5;
    const int wm = (warp >> 2) * 64;
    const int wn = (warp & 3) * 32;

    const int rowA0 = blockIdx.y * 128;
    const int colB0 = blockIdx.x * 128;

    float acc[4][4][4];
    #pragma unroll
    for (int i = 0; i < 4; ++i)
        #pragma unroll
        for (int j = 0; j < 4; ++j)
            #pragma unroll
            for (int r = 0; r < 4; ++r) acc[i][j][r] = 0.f;

    const int KT = K >> 5;   // K / 32 elements per stage

    auto load_stage = [&](int st, int kt) {
        const size_t k0b = (size_t)kt * 64;   // byte offset along K
        #pragma unroll
        for (int c = 0; c < 2; ++c) {
            int chunk = tid + c * 256;        // 0..511
            int row  = chunk >> 2;
            int c16  = (chunk & 3) << 4;      // byte offset within 64B row slab
            cp16(smem_u32(&sA[st][row][c16]),
                 (const char*)A + (size_t)(rowA0 + row) * (K * 2) + k0b + c16);
            cp16(smem_u32(&sB[st][row][c16]),
                 (const char*)B + (size_t)(colB0 + row) * (K * 2) + k0b + c16);
        }
        cp_commit();
    };

    load_stage(0, 0);

    // ldmatrix lane->row/col (b16 8x8 = 8 rows x 16B)
    const int a_row = lane & 15;               // rows 0..15 of the 16x16 tile
    const int a_sel = (lane >> 4) << 4;        // 0 / 16 bytes (k halves 0-7 / 8-15)
    const int b_row = (lane & 7) + (((lane >> 3) & 1) << 3);  // n row within 16
    const int b_sel = (lane >> 4) << 4;        // k halves 0-7 / 8-15

    for (int kt = 0; kt < KT; ++kt) {
        const int buf = kt & 1;
        if (kt + 1 < KT) {
            load_stage(buf ^ 1, kt + 1);
            cp_wait<1>();
        } else {
            cp_wait<0>();
        }
        __syncthreads();

        #pragma unroll
        for (int ks = 0; ks < 2; ++ks) {       // two k16 slabs in BK=32
            const int kb = ks * 32;            // byte offset
            unsigned a[4][4], b[4][2];
            #pragma unroll
            for (int i = 0; i < 4; ++i) {
                unsigned addr = smem_u32(&sA[buf][wm + i * 16 + a_row][kb + a_sel]);
                ldsm4(a[i][0], a[i][1], a[i][2], a[i][3], addr);
            }
            #pragma unroll
            for (int j2 = 0; j2 < 2; ++j2) {
                unsigned addr = smem_u32(&sB[buf][wn + j2 * 16 + b_row][kb + b_sel]);
                // r0=(n0-7,k0-7) r1=(n8-15,k0-7) r2=(n0-7,k8-15) r3=(n8-15,k8-15)
                ldsm4(b[2 * j2][0], b[2 * j2 + 1][0],
                      b[2 * j2][1], b[2 * j2 + 1][1], addr);
            }
            #pragma unroll
            for (int i = 0; i < 4; ++i)
                #pragma unroll
                for (int j = 0; j < 4; ++j)
                    MMA_BF16(acc[i][j], a[i], b[j]);
        }
        __syncthreads();
    }

    // epilogue: gelu + absmax(h)
    const float sa = fmaxf(__uint_as_float(g_amax[0]), 1e-8f) / 127.f;
    const float sb = fmaxf(__uint_as_float(g_amax[1]), 1e-8f) / 127.f;
    const float s  = sa * sb;

    float lmax = 0.f;
    #pragma unroll
    for (int i = 0; i < 4; ++i) {
        #pragma unroll
        for (int j = 0; j < 4; ++j) {
            const int row0 = rowA0 + wm + i * 16 + (lane >> 2);
            const int col0 = colB0 + wn + j * 8 + (lane & 3) * 2;
            #pragma unroll
            for (int rr = 0; rr < 2; ++rr) {
                const int row = row0 + rr * 8;
                float t0 = fmaf(acc[i][j][rr * 2 + 0], s, bias[col0 + 0]);
                float t1 = fmaf(acc[i][j][rr * 2 + 1], s, bias[col0 + 1]);
                t0 = 0.5f * t0 * (1.f + erff(t0 * 0.70710678118654752f));
                t1 = 0.5f * t1 * (1.f + erff(t1 * 0.70710678118654752f));
                lmax = fmaxf(lmax, fmaxf(fabsf(t0), fabsf(t1)));
                float2 v; v.x = t0; v.y = t1;
                *(float2*)(Cout + (size_t)row * N + col0) = v;
            }
        }
    }
    #pragma unroll
    for (int o = 16; o > 0; o >>= 1)
        lmax = fmaxf(lmax, __shfl_xor_sync(0xffffffffu, lmax, o));
    if (lane == 0) atomicMax(&g_amax[3], __float_as_uint(lmax));
}

// ---------------- int8 GEMM2 (mma.sync m16n8k32 + ldmatrix) ------------------
__global__ __launch_bounds__(256, 2)
void gemm_s8_kernel(const signed char* __restrict__ A,
                    const signed char* __restrict__ B,
                    const float* __restrict__ bias,
                    float* __restrict__ Cout,
                    int K, int N) {
    __shared__ signed char sA[2][128][80];
    __shared__ signed char sB[2][128][80];

    const int tid  = threadIdx.x;
    const int lane = tid & 31;
    const int warp = tid >> 5;
    const int wm = (warp >> 2) * 64;
    const int wn = (warp & 3) * 32;

    const int rowA0 = blockIdx.y * 128;
    const int colB0 = blockIdx.x * 128;

    int acc[4][4][4];
    #pragma unroll
    for (int i = 0; i < 4; ++i)
        #pragma unroll
        for (int j = 0; j < 4; ++j)
            #pragma unroll
            for (int r = 0; r < 4; ++r) acc[i][j][r] = 0;

    const int KT = K >> 6;

    auto load_stage = [&](int st, int kt) {
        const int k0 = kt << 6;
        #pragma unroll
        for (int c = 0; c < 2; ++c) {
            int chunk = tid + c * 256;
            int row  = chunk >> 2;
            int c16  = (chunk & 3) << 4;
            cp16(smem_u32(&sA[st][row][c16]),
                 A + (size_t)(rowA0 + row) * K + k0 + c16);
            cp16(smem_u32(&sB[st][row][c16]),
                 B + (size_t)(colB0 + row) * K + k0 + c16);
        }
        cp_commit();
    };

    load_stage(0, 0);

    const int sub = lane >> 3;
    const int a_row = (lane & 7) + ((sub & 1) << 3);
    const int a_col = (sub >> 1) << 4;
    const int b_row = (lane & 7) + ((sub >> 1) << 3);
    const int b_col = (sub & 1) << 4;

    for (int kt = 0; kt < KT; ++kt) {
        const int buf = kt & 1;
        if (kt + 1 < KT) {
            load_stage(buf ^ 1, kt + 1);
            cp_wait<1>();
        } else {
            cp_wait<0>();
        }
        __syncthreads();

        #pragma unroll
        for (int ks = 0; ks < 2; ++ks) {
            unsigned a[4][4], b[4][2];
            #pragma unroll
            for (int i = 0; i < 4; ++i) {
                unsigned addr = smem_u32(
                    &sA[buf][wm + i * 16 + a_row][ks * 32 + a_col]);
                ldsm4(a[i][0], a[i][1], a[i][2], a[i][3], addr);
            }
            #pragma unroll
            for (int j2 = 0; j2 < 2; ++j2) {
                unsigned addr = smem_u32(
                    &sB[buf][wn + j2 * 16 + b_row][ks * 32 + b_col]);
                ldsm4(b[2 * j2][0], b[2 * j2][1],
                      b[2 * j2 + 1][0], b[2 * j2 + 1][1], addr);
            }
            #pragma unroll
            for (int i = 0; i < 4; ++i)
                #pragma unroll
                for (int j = 0; j < 4; ++j)
                    MMA_S8(acc[i][j], a[i], b[j]);
        }
        __syncthreads();
    }

    const float sa = fmaxf(__uint_as_float(g_amax[3]), 1e-8f) / 127.f;
    const float sb = fmaxf(__uint_as_float(g_amax[2]), 1e-8f) / 127.f;
    const float s  = sa * sb;

    #pragma unroll
    for (int i = 0; i < 4; ++i) {
        #pragma unroll
        for (int j = 0; j < 4; ++j) {
            const int row0 = rowA0 + wm + i * 16 + (lane >> 2);
            const int col0 = colB0 + wn + j * 8 + (lane & 3) * 2;
            #pragma unroll
            for (int rr = 0; rr < 2; ++rr) {
                const int row = row0 + rr * 8;
                float2 v;
                v.x = fmaf((float)acc[i][j][rr * 2 + 0], s, bias[col0 + 0]);
                v.y = fmaf((float)acc[i][j][rr * 2 + 1], s, bias[col0 + 1]);
                *(float2*)(Cout + (size_t)row * N + col0) = v;
            }
        }
    }
}

// ---------------- launch ----------------------------------------------------
extern "C" void kernel_launch(void* const* d_in, const int* in_sizes, int n_in,
                              void* d_out, int out_size) {
    const float* x  = (const float*)d_in[0];
    const float* w1 = (const float*)d_in[1];
    const float* b1 = (const float*)d_in[2];
    const float* w2 = (const float*)d_in[3];
    const float* b2 = (const float*)d_in[4];
    float* out = (float*)d_out;

    __nv_bfloat16 *xb, *w1b;
    signed char *wq2, *hq;
    float* hbuf;
    cudaGetSymbolAddress((void**)&xb,   g_xb);
    cudaGetSymbolAddress((void**)&w1b,  g_w1b);
    cudaGetSymbolAddress((void**)&wq2,  g_wq2);
    cudaGetSymbolAddress((void**)&hbuf, g_h);
    cudaGetSymbolAddress((void**)&hq,   g_hq);

    // launch order matters for ncu (-s 5 -c 1 -> captures launch #6 = gemm2)
    init_kernel<<<1, 32>>>();
    absmax_all_kernel<<<1536, 256>>>((const float4*)x, (const float4*)w1,
                                     (const float4*)w2);
    quant_all_kernel<<<24576, 256>>>((const float4*)x, (const float4*)w1,
                                     (const float4*)w2);
    {
        dim3 grid(H_DIM / 128, M_TOK / 128);
        gemm_bf16_kernel<<<grid, 256>>>(xb, w1b, b1, hbuf, D_DIM, H_DIM);
    }
    {
        size_t n4 = ((size_t)M_TOK * H_DIM) / 4;
        quant_h_kernel<<<(unsigned)(n4 / 256), 256>>>((const float4*)hbuf,
                                                      (char4*)hq, (int)n4);
    }
    {
        dim3 grid(D_DIM / 128, M_TOK / 128);
        gemm_s8_kernel<<<grid, 256>>>(hq, wq2, b2, out, H_DIM, D_DIM);
    }
    (void)in_sizes; (void)n_in; (void)out_size;
}

// round 6
// speedup vs baseline: 1.8002x; 1.4415x over previous
#include <cuda_runtime.h>
#include <cuda_bf16.h>
#include <cstdint>

#define M_TOK   16384
#define D_DIM   1024
#define H_DIM   4096

// ---------------- scratch (static device memory; no allocations) -----------
__device__ __align__(16) __nv_bfloat16 g_xb [M_TOK * D_DIM];          // 33.5 MB
__device__ __align__(16) __nv_bfloat16 g_w1b[H_DIM * D_DIM];          // 8.4 MB
__device__ __align__(16) __nv_bfloat16 g_w2b[D_DIM * H_DIM];          // 8.4 MB
__device__ __align__(16) float         g_h  [(size_t)M_TOK * H_DIM];  // 256 MB
__device__ __align__(16) __nv_bfloat16 g_hb [(size_t)M_TOK * H_DIM];  // 128 MB
__device__ unsigned g_amax[4];   // 0: x, 1: w1, 2: w2, 3: h (fp32 bits)

// ---------------- helpers ---------------------------------------------------
__device__ __forceinline__ unsigned smem_u32(const void* p) {
    return (unsigned)__cvta_generic_to_shared(p);
}
__device__ __forceinline__ void cp16(unsigned dst, const void* src) {
    asm volatile("cp.async.cg.shared.global [%0], [%1], 16;\n" :: "r"(dst), "l"(src));
}
__device__ __forceinline__ void cp_commit() {
    asm volatile("cp.async.commit_group;\n");
}
template <int N>
__device__ __forceinline__ void cp_wait() {
    asm volatile("cp.async.wait_group %0;\n" :: "n"(N));
}
__device__ __forceinline__ void ldsm4(unsigned& r0, unsigned& r1, unsigned& r2,
                                      unsigned& r3, unsigned addr) {
    asm volatile("ldmatrix.sync.aligned.m8n8.x4.shared.b16 {%0,%1,%2,%3}, [%4];"
                 : "=r"(r0), "=r"(r1), "=r"(r2), "=r"(r3) : "r"(addr));
}

#define MMA_BF16(d, a, b)                                                      \
    asm volatile(                                                              \
        "mma.sync.aligned.m16n8k16.row.col.f32.bf16.bf16.f32 "                 \
        "{%0,%1,%2,%3},{%4,%5,%6,%7},{%8,%9},{%0,%1,%2,%3};"                   \
        : "+f"(d[0]), "+f"(d[1]), "+f"(d[2]), "+f"(d[3])                       \
        : "r"(a[0]), "r"(a[1]), "r"(a[2]), "r"(a[3]), "r"(b[0]), "r"(b[1]))

// ---------------- fused prep kernels ----------------------------------------
__global__ void init_kernel() {
    if (threadIdx.x < 4) g_amax[threadIdx.x] = 0u;
}

// blocks [0,1024): x | [1024,1280): w1 | [1280,1536): w2
__global__ void absmax_all_kernel(const float4* __restrict__ x,
                                  const float4* __restrict__ w1,
                                  const float4* __restrict__ w2) {
    const float4* p;
    int n4, slot, lb, nb;
    int b = blockIdx.x;
    if (b < 1024)      { p = x;  n4 = (M_TOK * D_DIM) / 4; slot = 0; lb = b;        nb = 1024; }
    else if (b < 1280) { p = w1; n4 = (H_DIM * D_DIM) / 4; slot = 1; lb = b - 1024; nb = 256; }
    else               { p = w2; n4 = (D_DIM * H_DIM) / 4; slot = 2; lb = b - 1280; nb = 256; }

    float m = 0.f;
    for (int i = lb * blockDim.x + threadIdx.x; i < n4; i += nb * blockDim.x) {
        float4 v = p[i];
        m = fmaxf(m, fmaxf(fmaxf(fabsf(v.x), fabsf(v.y)),
                           fmaxf(fabsf(v.z), fabsf(v.w))));
    }
    #pragma unroll
    for (int o = 16; o > 0; o >>= 1)
        m = fmaxf(m, __shfl_xor_sync(0xffffffffu, m, o));
    __shared__ float sm[8];
    if ((threadIdx.x & 31) == 0) sm[threadIdx.x >> 5] = m;
    __syncthreads();
    if (threadIdx.x == 0) {
        float v = sm[0];
        #pragma unroll
        for (int i = 1; i < 8; ++i) v = fmaxf(v, sm[i]);
        atomicMax(&g_amax[slot], __float_as_uint(v));
    }
}

__device__ __forceinline__ float quantf(float v, float scale) {
    return fminf(fmaxf(rintf(v / scale), -127.f), 127.f);
}
__device__ __forceinline__ unsigned short bf16bits(float v) {
    __nv_bfloat16 h = __float2bfloat16(v);
    return *(unsigned short*)&h;
}

// blocks [0,16384): x | [16384,20480): w1 | [20480,24576): w2  (all -> bf16 ints)
__global__ void quant_all_kernel(const float4* __restrict__ x,
                                 const float4* __restrict__ w1,
                                 const float4* __restrict__ w2) {
    int b = blockIdx.x;
    const float4* src;
    ushort4* dst;
    int i, slot;
    if (b < 16384)      { src = x;  dst = (ushort4*)g_xb;  i = b * blockDim.x + threadIdx.x;            slot = 0; }
    else if (b < 20480) { src = w1; dst = (ushort4*)g_w1b; i = (b - 16384) * blockDim.x + threadIdx.x;  slot = 1; }
    else                { src = w2; dst = (ushort4*)g_w2b; i = (b - 20480) * blockDim.x + threadIdx.x;  slot = 2; }
    float scale = fmaxf(__uint_as_float(g_amax[slot]), 1e-8f) / 127.f;
    float4 v = src[i];
    ushort4 o;
    o.x = bf16bits(quantf(v.x, scale));
    o.y = bf16bits(quantf(v.y, scale));
    o.z = bf16bits(quantf(v.z, scale));
    o.w = bf16bits(quantf(v.w, scale));
    dst[i] = o;
}

__global__ void quant_h_kernel(const float4* __restrict__ x,
                               ushort4* __restrict__ q, int n4) {
    float scale = fmaxf(__uint_as_float(g_amax[3]), 1e-8f) / 127.f;
    int i = blockIdx.x * blockDim.x + threadIdx.x;
    if (i < n4) {
        float4 v = x[i];
        ushort4 o;
        o.x = bf16bits(quantf(v.x, scale));
        o.y = bf16bits(quantf(v.y, scale));
        o.z = bf16bits(quantf(v.z, scale));
        o.w = bf16bits(quantf(v.w, scale));
        q[i] = o;
    }
}

// ---------------- bf16 GEMM (mma.sync m16n8k16 + ldmatrix) -------------------
// C[M,N] = A[M,K](bf16 row-major) * B[N,K](bf16 row-major as col-major op)
// BM=128, BN=128, BK=32 elements (64B), 256 threads, 8 warps, warp 64x32.
// EPI 0: v = acc*s + bias; exact gelu; store fp32; absmax -> g_amax[3]
// EPI 1: v = acc*s + bias; store fp32
template <int EPI>
__global__ __launch_bounds__(256, 2)
void gemm_bf16_kernel(const __nv_bfloat16* __restrict__ A,
                      const __nv_bfloat16* __restrict__ B,
                      const float* __restrict__ bias,
                      float* __restrict__ Cout,
                      int K, int N, int saslot, int sbslot) {
    __shared__ signed char sA[2][128][80];   // 32 bf16 = 64B data + 16B pad
    __shared__ signed char sB[2][128][80];

    const int tid  = threadIdx.x;
    const int lane = tid & 31;
    const int warp = tid >> 5;
    const int wm = (warp >> 2) * 64;
    const int wn = (warp & 3) * 32;

    const int rowA0 = blockIdx.y * 128;
    const int colB0 = blockIdx.x * 128;

    float acc[4][4][4];
    #pragma unroll
    for (int i = 0; i < 4; ++i)
        #pragma unroll
        for (int j = 0; j < 4; ++j)
            #pragma unroll
            for (int r = 0; r < 4; ++r) acc[i][j][r] = 0.f;

    const int KT = K >> 5;   // K / 32 elements per stage

    auto load_stage = [&](int st, int kt) {
        const size_t k0b = (size_t)kt * 64;   // byte offset along K
        #pragma unroll
        for (int c = 0; c < 2; ++c) {
            int chunk = tid + c * 256;        // 0..511
            int row  = chunk >> 2;
            int c16  = (chunk & 3) << 4;
            cp16(smem_u32(&sA[st][row][c16]),
                 (const char*)A + (size_t)(rowA0 + row) * (K * 2) + k0b + c16);
            cp16(smem_u32(&sB[st][row][c16]),
                 (const char*)B + (size_t)(colB0 + row) * (K * 2) + k0b + c16);
        }
        cp_commit();
    };

    load_stage(0, 0);

    // ldmatrix lane->row/col (b16 8x8 = 8 rows x 16B)
    const int a_row = lane & 15;
    const int a_sel = (lane >> 4) << 4;
    const int b_row = (lane & 7) + (((lane >> 3) & 1) << 3);
    const int b_sel = (lane >> 4) << 4;

    for (int kt = 0; kt < KT; ++kt) {
        const int buf = kt & 1;
        if (kt + 1 < KT) {
            load_stage(buf ^ 1, kt + 1);
            cp_wait<1>();
        } else {
            cp_wait<0>();
        }
        __syncthreads();

        #pragma unroll
        for (int ks = 0; ks < 2; ++ks) {       // two k16 slabs in BK=32
            const int kb = ks * 32;            // byte offset
            unsigned a[4][4], b[4][2];
            #pragma unroll
            for (int i = 0; i < 4; ++i) {
                unsigned addr = smem_u32(&sA[buf][wm + i * 16 + a_row][kb + a_sel]);
                ldsm4(a[i][0], a[i][1], a[i][2], a[i][3], addr);
            }
            #pragma unroll
            for (int j2 = 0; j2 < 2; ++j2) {
                unsigned addr = smem_u32(&sB[buf][wn + j2 * 16 + b_row][kb + b_sel]);
                // r0=(n0-7,k0-7) r1=(n8-15,k0-7) r2=(n0-7,k8-15) r3=(n8-15,k8-15)
                ldsm4(b[2 * j2][0], b[2 * j2 + 1][0],
                      b[2 * j2][1], b[2 * j2 + 1][1], addr);
            }
            #pragma unroll
            for (int i = 0; i < 4; ++i)
                #pragma unroll
                for (int j = 0; j < 4; ++j)
                    MMA_BF16(acc[i][j], a[i], b[j]);
        }
        __syncthreads();
    }

    // epilogue
    const float sa = fmaxf(__uint_as_float(g_amax[saslot]), 1e-8f) / 127.f;
    const float sb = fmaxf(__uint_as_float(g_amax[sbslot]), 1e-8f) / 127.f;
    const float s  = sa * sb;

    float lmax = 0.f;
    #pragma unroll
    for (int i = 0; i < 4; ++i) {
        #pragma unroll
        for (int j = 0; j < 4; ++j) {
            const int row0 = rowA0 + wm + i * 16 + (lane >> 2);
            const int col0 = colB0 + wn + j * 8 + (lane & 3) * 2;
            #pragma unroll
            for (int rr = 0; rr < 2; ++rr) {
                const int row = row0 + rr * 8;
                float t0 = fmaf(acc[i][j][rr * 2 + 0], s, bias[col0 + 0]);
                float t1 = fmaf(acc[i][j][rr * 2 + 1], s, bias[col0 + 1]);
                if (EPI == 0) {
                    t0 = 0.5f * t0 * (1.f + erff(t0 * 0.70710678118654752f));
                    t1 = 0.5f * t1 * (1.f + erff(t1 * 0.70710678118654752f));
                    lmax = fmaxf(lmax, fmaxf(fabsf(t0), fabsf(t1)));
                }
                float2 v; v.x = t0; v.y = t1;
                *(float2*)(Cout + (size_t)row * N + col0) = v;
            }
        }
    }
    if (EPI == 0) {
        #pragma unroll
        for (int o = 16; o > 0; o >>= 1)
            lmax = fmaxf(lmax, __shfl_xor_sync(0xffffffffu, lmax, o));
        if (lane == 0) atomicMax(&g_amax[3], __float_as_uint(lmax));
    }
}

// ---------------- launch ----------------------------------------------------
extern "C" void kernel_launch(void* const* d_in, const int* in_sizes, int n_in,
                              void* d_out, int out_size) {
    const float* x  = (const float*)d_in[0];
    const float* w1 = (const float*)d_in[1];
    const float* b1 = (const float*)d_in[2];
    const float* w2 = (const float*)d_in[3];
    const float* b2 = (const float*)d_in[4];
    float* out = (float*)d_out;

    __nv_bfloat16 *xb, *w1b, *w2b, *hb;
    float* hbuf;
    cudaGetSymbolAddress((void**)&xb,   g_xb);
    cudaGetSymbolAddress((void**)&w1b,  g_w1b);
    cudaGetSymbolAddress((void**)&w2b,  g_w2b);
    cudaGetSymbolAddress((void**)&hbuf, g_h);
    cudaGetSymbolAddress((void**)&hb,   g_hb);

    // launch order matters for ncu (-s 5 -c 1 -> captures launch #6 = gemm2)
    init_kernel<<<1, 32>>>();
    absmax_all_kernel<<<1536, 256>>>((const float4*)x, (const float4*)w1,
                                     (const float4*)w2);
    quant_all_kernel<<<24576, 256>>>((const float4*)x, (const float4*)w1,
                                     (const float4*)w2);
    {
        dim3 grid(H_DIM / 128, M_TOK / 128);
        gemm_bf16_kernel<0><<<grid, 256>>>(xb, w1b, b1, hbuf, D_DIM, H_DIM, 0, 1);
    }
    {
        size_t n4 = ((size_t)M_TOK * H_DIM) / 4;
        quant_h_kernel<<<(unsigned)(n4 / 256), 256>>>((const float4*)hbuf,
                                                      (ushort4*)hb, (int)n4);
    }
    {
        dim3 grid(D_DIM / 128, M_TOK / 128);
        gemm_bf16_kernel<1><<<grid, 256>>>(hb, w2b, b2, out, H_DIM, D_DIM, 3, 2);
    }
    (void)in_sizes; (void)n_in; (void)out_size;
}

// round 7
// speedup vs baseline: 2.2256x; 1.2363x over previous
#include <cuda_runtime.h>
#include <cuda_bf16.h>
#include <cstdint>

#define M_TOK   16384
#define D_DIM   1024
#define H_DIM   4096

// ---------------- scratch (static device memory; no allocations) -----------
__device__ __align__(16) __nv_bfloat16 g_xb [M_TOK * D_DIM];          // 33.5 MB
__device__ __align__(16) __nv_bfloat16 g_w1b[H_DIM * D_DIM];          // 8.4 MB
__device__ __align__(16) __nv_bfloat16 g_w2b[D_DIM * H_DIM];          // 8.4 MB
__device__ __align__(16) float         g_h  [(size_t)M_TOK * H_DIM];  // 256 MB
__device__ __align__(16) __nv_bfloat16 g_hb [(size_t)M_TOK * H_DIM];  // 128 MB
__device__ unsigned g_amax[4];   // 0: x, 1: w1, 2: w2, 3: h (fp32 bits)

// ---------------- helpers ---------------------------------------------------
__device__ __forceinline__ unsigned smem_u32(const void* p) {
    return (unsigned)__cvta_generic_to_shared(p);
}
__device__ __forceinline__ void cp16(unsigned dst, const void* src) {
    asm volatile("cp.async.cg.shared.global [%0], [%1], 16;\n" :: "r"(dst), "l"(src));
}
__device__ __forceinline__ void cp_commit() {
    asm volatile("cp.async.commit_group;\n");
}
template <int N>
__device__ __forceinline__ void cp_wait() {
    asm volatile("cp.async.wait_group %0;\n" :: "n"(N));
}
__device__ __forceinline__ void ldsm4(unsigned& r0, unsigned& r1, unsigned& r2,
                                      unsigned& r3, unsigned addr) {
    asm volatile("ldmatrix.sync.aligned.m8n8.x4.shared.b16 {%0,%1,%2,%3}, [%4];"
                 : "=r"(r0), "=r"(r1), "=r"(r2), "=r"(r3) : "r"(addr));
}

#define MMA_BF16(d, a, b)                                                      \
    asm volatile(                                                              \
        "mma.sync.aligned.m16n8k16.row.col.f32.bf16.bf16.f32 "                 \
        "{%0,%1,%2,%3},{%4,%5,%6,%7},{%8,%9},{%0,%1,%2,%3};"                   \
        : "+f"(d[0]), "+f"(d[1]), "+f"(d[2]), "+f"(d[3])                       \
        : "r"(a[0]), "r"(a[1]), "r"(a[2]), "r"(a[3]), "r"(b[0]), "r"(b[1]))

// ---------------- fused prep kernels ----------------------------------------
__global__ void init_kernel() {
    if (threadIdx.x < 4) g_amax[threadIdx.x] = 0u;
}

// blocks [0,1024): x | [1024,1280): w1 | [1280,1536): w2
__global__ void absmax_all_kernel(const float4* __restrict__ x,
                                  const float4* __restrict__ w1,
                                  const float4* __restrict__ w2) {
    const float4* p;
    int n4, slot, lb, nb;
    int b = blockIdx.x;
    if (b < 1024)      { p = x;  n4 = (M_TOK * D_DIM) / 4; slot = 0; lb = b;        nb = 1024; }
    else if (b < 1280) { p = w1; n4 = (H_DIM * D_DIM) / 4; slot = 1; lb = b - 1024; nb = 256; }
    else               { p = w2; n4 = (D_DIM * H_DIM) / 4; slot = 2; lb = b - 1280; nb = 256; }

    float m = 0.f;
    for (int i = lb * blockDim.x + threadIdx.x; i < n4; i += nb * blockDim.x) {
        float4 v = p[i];
        m = fmaxf(m, fmaxf(fmaxf(fabsf(v.x), fabsf(v.y)),
                           fmaxf(fabsf(v.z), fabsf(v.w))));
    }
    #pragma unroll
    for (int o = 16; o > 0; o >>= 1)
        m = fmaxf(m, __shfl_xor_sync(0xffffffffu, m, o));
    __shared__ float sm[8];
    if ((threadIdx.x & 31) == 0) sm[threadIdx.x >> 5] = m;
    __syncthreads();
    if (threadIdx.x == 0) {
        float v = sm[0];
        #pragma unroll
        for (int i = 1; i < 8; ++i) v = fmaxf(v, sm[i]);
        atomicMax(&g_amax[slot], __float_as_uint(v));
    }
}

__device__ __forceinline__ float quantf(float v, float scale) {
    return fminf(fmaxf(rintf(v / scale), -127.f), 127.f);
}
__device__ __forceinline__ unsigned short bf16bits(float v) {
    __nv_bfloat16 h = __float2bfloat16(v);
    return *(unsigned short*)&h;
}

// blocks [0,16384): x | [16384,20480): w1 | [20480,24576): w2  (all -> bf16 ints)
__global__ void quant_all_kernel(const float4* __restrict__ x,
                                 const float4* __restrict__ w1,
                                 const float4* __restrict__ w2) {
    int b = blockIdx.x;
    const float4* src;
    ushort4* dst;
    int i, slot;
    if (b < 16384)      { src = x;  dst = (ushort4*)g_xb;  i = b * blockDim.x + threadIdx.x;            slot = 0; }
    else if (b < 20480) { src = w1; dst = (ushort4*)g_w1b; i = (b - 16384) * blockDim.x + threadIdx.x;  slot = 1; }
    else                { src = w2; dst = (ushort4*)g_w2b; i = (b - 20480) * blockDim.x + threadIdx.x;  slot = 2; }
    float scale = fmaxf(__uint_as_float(g_amax[slot]), 1e-8f) / 127.f;
    float4 v = src[i];
    ushort4 o;
    o.x = bf16bits(quantf(v.x, scale));
    o.y = bf16bits(quantf(v.y, scale));
    o.z = bf16bits(quantf(v.z, scale));
    o.w = bf16bits(quantf(v.w, scale));
    dst[i] = o;
}

__global__ void quant_h_kernel(const float4* __restrict__ x,
                               ushort4* __restrict__ q, int n4) {
    float scale = fmaxf(__uint_as_float(g_amax[3]), 1e-8f) / 127.f;
    int i = blockIdx.x * blockDim.x + threadIdx.x;
    if (i < n4) {
        float4 v = x[i];
        ushort4 o;
        o.x = bf16bits(quantf(v.x, scale));
        o.y = bf16bits(quantf(v.y, scale));
        o.z = bf16bits(quantf(v.z, scale));
        o.w = bf16bits(quantf(v.w, scale));
        q[i] = o;
    }
}

// ---------------- bf16 GEMM (warp 64x64, BK=64, 3-stage, swizzled) -----------
// C[M,N] = A[M,K](bf16 row-major) * B[N,K](bf16 row-major as col-major op)
// Block 128x128, 128 threads (4 warps, 2x2), warp tile 64x64, BK=64 (128B).
// Smem: XOR swizzle, stride 128B, stage = 2*128*128 = 32KB, 3 stages = 96KB.
// EPI 0: v = acc*s + bias; exact gelu; store fp32; absmax -> g_amax[3]
// EPI 1: v = acc*s + bias; store fp32
#define GSTAGE  32768
#define GB_OFF  16384

template <int EPI>
__global__ __launch_bounds__(128, 2)
void gemm_bf16_kernel(const __nv_bfloat16* __restrict__ A,
                      const __nv_bfloat16* __restrict__ B,
                      const float* __restrict__ bias,
                      float* __restrict__ Cout,
                      int K, int N, int saslot, int sbslot) {
    extern __shared__ __align__(128) char smem[];
    const uint32_t sbase = smem_u32(smem);

    const int tid  = threadIdx.x;
    const int lane = tid & 31;
    const int warp = tid >> 5;
    const int wm = (warp >> 1) * 64;   // warp M base: 0 / 64
    const int wn = (warp & 1) * 64;    // warp N base: 0 / 64

    const int rowA0 = blockIdx.y * 128;
    const int colB0 = blockIdx.x * 128;

    float acc[4][8][4];
    #pragma unroll
    for (int i = 0; i < 4; ++i)
        #pragma unroll
        for (int j = 0; j < 8; ++j)
            #pragma unroll
            for (int r = 0; r < 4; ++r) acc[i][j][r] = 0.f;

    const int KT = K >> 6;   // K / 64 elements (128B) per stage
    const size_t Kb = (size_t)K * 2;  // row pitch in bytes

    // loader: per stage, A: 128 rows x 8 16B-chunks, B: same. 128 threads.
    // thread handles chunks idx = tid + m*128, m=0..7 for A then B.
    const int ld_row = tid >> 3;            // base row pattern  (16 rows per m)
    // Actually: idx = m*128 + tid -> row = idx>>3 = (m<<4) + (tid>>3), col=(tid&7)
    const int ld_c16 = (tid & 7) << 4;
    auto load_stage = [&](int st, int kt) {
        const uint32_t stoff = sbase + st * GSTAGE;
        const size_t k0b = (size_t)kt * 128;
        const char* Ab = (const char*)A + (size_t)rowA0 * Kb + k0b + ld_c16;
        const char* Bb = (const char*)B + (size_t)colB0 * Kb + k0b + ld_c16;
        #pragma unroll
        for (int m = 0; m < 8; ++m) {
            const int row = (m << 4) + ld_row;
            const uint32_t sw = (uint32_t)(row * 128 + (ld_c16 ^ ((row & 7) << 4)));
            cp16(stoff + sw,          Ab + (size_t)row * Kb);
            cp16(stoff + GB_OFF + sw, Bb + (size_t)row * Kb);
        }
        cp_commit();
    };

    load_stage(0, 0);
    load_stage(1, 1);

    // ldmatrix lane geometry (swizzle term constant per lane: row&7 invariant)
    const int a_row = lane & 15;                               // 16 rows
    const int a_sel = (lane >> 4) << 4;                        // 0/16 B
    const int b_row = (lane & 7) + (((lane >> 3) & 1) << 3);   // 16 n-rows
    const int b_sel = (lane >> 4) << 4;
    const uint32_t a_swx = (uint32_t)((a_row & 7) << 4);
    const uint32_t b_swx = (uint32_t)((b_row & 7) << 4);

    for (int kt = 0; kt < KT; ++kt) {
        if (kt == KT - 1) cp_wait<0>(); else cp_wait<1>();
        __syncthreads();
        if (kt + 2 < KT) load_stage((kt + 2) % 3, kt + 2);

        const uint32_t st = sbase + (kt % 3) * GSTAGE;
        const uint32_t aBase = st + (uint32_t)((wm + a_row) * 128);
        const uint32_t bBase = st + GB_OFF + (uint32_t)((wn + b_row) * 128);

        #pragma unroll
        for (int ks = 0; ks < 4; ++ks) {       // four k16 slabs in BK=64
            const uint32_t kb = ks * 32;       // byte offset along K
            unsigned a[4][4], b[8][2];
            #pragma unroll
            for (int i = 0; i < 4; ++i) {
                unsigned addr = aBase + (uint32_t)(i * 16 * 128)
                              + ((kb + a_sel) ^ a_swx);
                ldsm4(a[i][0], a[i][1], a[i][2], a[i][3], addr);
            }
            #pragma unroll
            for (int jg = 0; jg < 4; ++jg) {
                unsigned addr = bBase + (uint32_t)(jg * 16 * 128)
                              + ((kb + b_sel) ^ b_swx);
                // r0=(n0-7,k0-7) r1=(n8-15,k0-7) r2=(n0-7,k8-15) r3=(n8-15,k8-15)
                ldsm4(b[2 * jg][0], b[2 * jg + 1][0],
                      b[2 * jg][1], b[2 * jg + 1][1], addr);
            }
            #pragma unroll
            for (int i = 0; i < 4; ++i)
                #pragma unroll
                for (int j = 0; j < 8; ++j)
                    MMA_BF16(acc[i][j], a[i], b[j]);
        }
    }

    // epilogue
    const float sa = fmaxf(__uint_as_float(g_amax[saslot]), 1e-8f) / 127.f;
    const float sb = fmaxf(__uint_as_float(g_amax[sbslot]), 1e-8f) / 127.f;
    const float s  = sa * sb;

    float lmax = 0.f;
    #pragma unroll
    for (int i = 0; i < 4; ++i) {
        #pragma unroll
        for (int j = 0; j < 8; ++j) {
            const int row0 = rowA0 + wm + i * 16 + (lane >> 2);
            const int col0 = colB0 + wn + j * 8 + (lane & 3) * 2;
            #pragma unroll
            for (int rr = 0; rr < 2; ++rr) {
                const int row = row0 + rr * 8;
                float t0 = fmaf(acc[i][j][rr * 2 + 0], s, bias[col0 + 0]);
                float t1 = fmaf(acc[i][j][rr * 2 + 1], s, bias[col0 + 1]);
                if (EPI == 0) {
                    t0 = 0.5f * t0 * (1.f + erff(t0 * 0.70710678118654752f));
                    t1 = 0.5f * t1 * (1.f + erff(t1 * 0.70710678118654752f));
                    lmax = fmaxf(lmax, fmaxf(fabsf(t0), fabsf(t1)));
                }
                float2 v; v.x = t0; v.y = t1;
                *(float2*)(Cout + (size_t)row * N + col0) = v;
            }
        }
    }
    if (EPI == 0) {
        #pragma unroll
        for (int o = 16; o > 0; o >>= 1)
            lmax = fmaxf(lmax, __shfl_xor_sync(0xffffffffu, lmax, o));
        if (lane == 0) atomicMax(&g_amax[3], __float_as_uint(lmax));
    }
}

#define GEMM_SMEM (3 * GSTAGE)   // 98304 B

// ---------------- launch ----------------------------------------------------
extern "C" void kernel_launch(void* const* d_in, const int* in_sizes, int n_in,
                              void* d_out, int out_size) {
    const float* x  = (const float*)d_in[0];
    const float* w1 = (const float*)d_in[1];
    const float* b1 = (const float*)d_in[2];
    const float* w2 = (const float*)d_in[3];
    const float* b2 = (const float*)d_in[4];
    float* out = (float*)d_out;

    __nv_bfloat16 *xb, *w1b, *w2b, *hb;
    float* hbuf;
    cudaGetSymbolAddress((void**)&xb,   g_xb);
    cudaGetSymbolAddress((void**)&w1b,  g_w1b);
    cudaGetSymbolAddress((void**)&w2b,  g_w2b);
    cudaGetSymbolAddress((void**)&hbuf, g_h);
    cudaGetSymbolAddress((void**)&hb,   g_hb);

    cudaFuncSetAttribute(gemm_bf16_kernel<0>,
                         cudaFuncAttributeMaxDynamicSharedMemorySize, GEMM_SMEM);
    cudaFuncSetAttribute(gemm_bf16_kernel<1>,
                         cudaFuncAttributeMaxDynamicSharedMemorySize, GEMM_SMEM);

    // launch order matters for ncu (-s 5 -c 1 -> captures launch #6 = gemm2)
    init_kernel<<<1, 32>>>();
    absmax_all_kernel<<<1536, 256>>>((const float4*)x, (const float4*)w1,
                                     (const float4*)w2);
    quant_all_kernel<<<24576, 256>>>((const float4*)x, (const float4*)w1,
                                     (const float4*)w2);
    {
        dim3 grid(H_DIM / 128, M_TOK / 128);
        gemm_bf16_kernel<0><<<grid, 128, GEMM_SMEM>>>(xb, w1b, b1, hbuf,
                                                      D_DIM, H_DIM, 0, 1);
    }
    {
        size_t n4 = ((size_t)M_TOK * H_DIM) / 4;
        quant_h_kernel<<<(unsigned)(n4 / 256), 256>>>((const float4*)hbuf,
                                                      (ushort4*)hb, (int)n4);
    }
    {
        dim3 grid(D_DIM / 128, M_TOK / 128);
        gemm_bf16_kernel<1><<<grid, 128, GEMM_SMEM>>>(hb, w2b, b2, out,
                                                      H_DIM, D_DIM, 3, 2);
    }
    (void)in_sizes; (void)n_in; (void)out_size;
}

// round 8
// speedup vs baseline: 2.2587x; 1.0148x over previous
#include <cuda_runtime.h>
#include <cuda_bf16.h>
#include <cstdint>

#define M_TOK   16384
#define D_DIM   1024
#define H_DIM   4096

// ---------------- scratch (static device memory; no allocations) -----------
__device__ __align__(16) __nv_bfloat16 g_xb [M_TOK * D_DIM];          // 33.5 MB
__device__ __align__(16) __nv_bfloat16 g_w1b[H_DIM * D_DIM];          // 8.4 MB
__device__ __align__(16) __nv_bfloat16 g_w2b[D_DIM * H_DIM];          // 8.4 MB
__device__ __align__(16) float         g_h  [(size_t)M_TOK * H_DIM];  // 256 MB
__device__ __align__(16) __nv_bfloat16 g_hb [(size_t)M_TOK * H_DIM];  // 128 MB
__device__ unsigned g_amax[4];   // 0: x, 1: w1, 2: w2, 3: h (fp32 bits)

// ---------------- helpers ---------------------------------------------------
__device__ __forceinline__ unsigned smem_u32(const void* p) {
    return (unsigned)__cvta_generic_to_shared(p);
}
__device__ __forceinline__ void cp16(unsigned dst, const void* src) {
    asm volatile("cp.async.cg.shared.global [%0], [%1], 16;\n" :: "r"(dst), "l"(src));
}
__device__ __forceinline__ void cp_commit() {
    asm volatile("cp.async.commit_group;\n");
}
template <int N>
__device__ __forceinline__ void cp_wait() {
    asm volatile("cp.async.wait_group %0;\n" :: "n"(N));
}
__device__ __forceinline__ void ldsm4(unsigned& r0, unsigned& r1, unsigned& r2,
                                      unsigned& r3, unsigned addr) {
    asm volatile("ldmatrix.sync.aligned.m8n8.x4.shared.b16 {%0,%1,%2,%3}, [%4];"
                 : "=r"(r0), "=r"(r1), "=r"(r2), "=r"(r3) : "r"(addr));
}

#define MMA_BF16(d, a, b)                                                      \
    asm volatile(                                                              \
        "mma.sync.aligned.m16n8k16.row.col.f32.bf16.bf16.f32 "                 \
        "{%0,%1,%2,%3},{%4,%5,%6,%7},{%8,%9},{%0,%1,%2,%3};"                   \
        : "+f"(d[0]), "+f"(d[1]), "+f"(d[2]), "+f"(d[3])                       \
        : "r"(a[0]), "r"(a[1]), "r"(a[2]), "r"(a[3]), "r"(b[0]), "r"(b[1]))

// ---------------- fused prep kernels ----------------------------------------
__global__ void init_kernel() {
    if (threadIdx.x < 4) g_amax[threadIdx.x] = 0u;
}

// blocks [0,1024): x | [1024,1280): w1 | [1280,1536): w2
__global__ void absmax_all_kernel(const float4* __restrict__ x,
                                  const float4* __restrict__ w1,
                                  const float4* __restrict__ w2) {
    const float4* p;
    int n4, slot, lb, nb;
    int b = blockIdx.x;
    if (b < 1024)      { p = x;  n4 = (M_TOK * D_DIM) / 4; slot = 0; lb = b;        nb = 1024; }
    else if (b < 1280) { p = w1; n4 = (H_DIM * D_DIM) / 4; slot = 1; lb = b - 1024; nb = 256; }
    else               { p = w2; n4 = (D_DIM * H_DIM) / 4; slot = 2; lb = b - 1280; nb = 256; }

    float m = 0.f;
    for (int i = lb * blockDim.x + threadIdx.x; i < n4; i += nb * blockDim.x) {
        float4 v = p[i];
        m = fmaxf(m, fmaxf(fmaxf(fabsf(v.x), fabsf(v.y)),
                           fmaxf(fabsf(v.z), fabsf(v.w))));
    }
    #pragma unroll
    for (int o = 16; o > 0; o >>= 1)
        m = fmaxf(m, __shfl_xor_sync(0xffffffffu, m, o));
    __shared__ float sm[8];
    if ((threadIdx.x & 31) == 0) sm[threadIdx.x >> 5] = m;
    __syncthreads();
    if (threadIdx.x == 0) {
        float v = sm[0];
        #pragma unroll
        for (int i = 1; i < 8; ++i) v = fmaxf(v, sm[i]);
        atomicMax(&g_amax[slot], __float_as_uint(v));
    }
}

__device__ __forceinline__ float quantf(float v, float scale) {
    return fminf(fmaxf(rintf(v / scale), -127.f), 127.f);
}
__device__ __forceinline__ unsigned short bf16bits(float v) {
    __nv_bfloat16 h = __float2bfloat16(v);
    return *(unsigned short*)&h;
}

// blocks [0,16384): x | [16384,20480): w1 | [20480,24576): w2  (all -> bf16 ints)
__global__ void quant_all_kernel(const float4* __restrict__ x,
                                 const float4* __restrict__ w1,
                                 const float4* __restrict__ w2) {
    int b = blockIdx.x;
    const float4* src;
    ushort4* dst;
    int i, slot;
    if (b < 16384)      { src = x;  dst = (ushort4*)g_xb;  i = b * blockDim.x + threadIdx.x;            slot = 0; }
    else if (b < 20480) { src = w1; dst = (ushort4*)g_w1b; i = (b - 16384) * blockDim.x + threadIdx.x;  slot = 1; }
    else                { src = w2; dst = (ushort4*)g_w2b; i = (b - 20480) * blockDim.x + threadIdx.x;  slot = 2; }
    float scale = fmaxf(__uint_as_float(g_amax[slot]), 1e-8f) / 127.f;
    float4 v = src[i];
    ushort4 o;
    o.x = bf16bits(quantf(v.x, scale));
    o.y = bf16bits(quantf(v.y, scale));
    o.z = bf16bits(quantf(v.z, scale));
    o.w = bf16bits(quantf(v.w, scale));
    dst[i] = o;
}

__global__ void quant_h_kernel(const float4* __restrict__ x,
                               ushort4* __restrict__ q, int n4) {
    float scale = fmaxf(__uint_as_float(g_amax[3]), 1e-8f) / 127.f;
    int i = blockIdx.x * blockDim.x + threadIdx.x;
    if (i < n4) {
        float4 v = x[i];
        ushort4 o;
        o.x = bf16bits(quantf(v.x, scale));
        o.y = bf16bits(quantf(v.y, scale));
        o.z = bf16bits(quantf(v.z, scale));
        o.w = bf16bits(quantf(v.w, scale));
        q[i] = o;
    }
}

// ---------------- bf16 GEMM (warp 64x64, BK=64, 3-stage, frag dbl-buf) -------
// C[M,N] = A[M,K](bf16 row-major) * B[N,K](bf16 row-major as col-major op)
// Block 128x128, 128 threads (4 warps, 2x2), warp tile 64x64, BK=64 (128B).
// Smem: XOR swizzle, stride 128B, stage = 32KB, 3 stages = 96KB dynamic.
// Inner loop double-buffers ldmatrix fragments across k16 slabs so LDSM
// (crossbar) overlaps MMA (tensor pipe).
#define GSTAGE  32768
#define GB_OFF  16384

template <int EPI>
__global__ __launch_bounds__(128, 2)
void gemm_bf16_kernel(const __nv_bfloat16* __restrict__ A,
                      const __nv_bfloat16* __restrict__ B,
                      const float* __restrict__ bias,
                      float* __restrict__ Cout,
                      int K, int N, int saslot, int sbslot) {
    extern __shared__ __align__(128) char smem[];
    const uint32_t sbase = smem_u32(smem);

    const int tid  = threadIdx.x;
    const int lane = tid & 31;
    const int warp = tid >> 5;
    const int wm = (warp >> 1) * 64;
    const int wn = (warp & 1) * 64;

    const int rowA0 = blockIdx.y * 128;
    const int colB0 = blockIdx.x * 128;

    float acc[4][8][4];
    #pragma unroll
    for (int i = 0; i < 4; ++i)
        #pragma unroll
        for (int j = 0; j < 8; ++j)
            #pragma unroll
            for (int r = 0; r < 4; ++r) acc[i][j][r] = 0.f;

    const int KT = K >> 6;
    const size_t Kb = (size_t)K * 2;

    const int ld_row = tid >> 3;
    const int ld_c16 = (tid & 7) << 4;
    auto load_stage = [&](int st, int kt) {
        const uint32_t stoff = sbase + st * GSTAGE;
        const size_t k0b = (size_t)kt * 128;
        const char* Ab = (const char*)A + (size_t)rowA0 * Kb + k0b + ld_c16;
        const char* Bb = (const char*)B + (size_t)colB0 * Kb + k0b + ld_c16;
        #pragma unroll
        for (int m = 0; m < 8; ++m) {
            const int row = (m << 4) + ld_row;
            const uint32_t sw = (uint32_t)(row * 128 + (ld_c16 ^ ((row & 7) << 4)));
            cp16(stoff + sw,          Ab + (size_t)row * Kb);
            cp16(stoff + GB_OFF + sw, Bb + (size_t)row * Kb);
        }
        cp_commit();
    };

    load_stage(0, 0);
    load_stage(1, 1);

    // ldmatrix lane geometry
    const int a_row = lane & 15;
    const int a_sel = (lane >> 4) << 4;
    const int b_row = (lane & 7) + (((lane >> 3) & 1) << 3);
    const int b_sel = (lane >> 4) << 4;
    const uint32_t a_swx = (uint32_t)((a_row & 7) << 4);
    const uint32_t b_swx = (uint32_t)((b_row & 7) << 4);

    // precomputed per-ks column offsets (swizzled)
    uint32_t acol[4], bcol[4];
    #pragma unroll
    for (int ks = 0; ks < 4; ++ks) {
        acol[ks] = (uint32_t)((ks * 32 + a_sel) ^ a_swx);
        bcol[ks] = (uint32_t)((ks * 32 + b_sel) ^ b_swx);
    }
    const uint32_t aRowOff = (uint32_t)((wm + a_row) * 128);
    const uint32_t bRowOff = (uint32_t)(GB_OFF + (wn + b_row) * 128);

    unsigned afr[2][4][4], bfr[2][8][2];

    #define LOAD_FRAGS(BUFIDX, ABASE, BBASE, KS)                               \
        do {                                                                   \
            _Pragma("unroll")                                                  \
            for (int i = 0; i < 4; ++i)                                        \
                ldsm4(afr[BUFIDX][i][0], afr[BUFIDX][i][1],                    \
                      afr[BUFIDX][i][2], afr[BUFIDX][i][3],                    \
                      (ABASE) + (uint32_t)(i * 16 * 128) + acol[KS]);          \
            _Pragma("unroll")                                                  \
            for (int jg = 0; jg < 4; ++jg)                                     \
                ldsm4(bfr[BUFIDX][2 * jg][0], bfr[BUFIDX][2 * jg + 1][0],      \
                      bfr[BUFIDX][2 * jg][1], bfr[BUFIDX][2 * jg + 1][1],      \
                      (BBASE) + (uint32_t)(jg * 16 * 128) + bcol[KS]);         \
        } while (0)

    for (int kt = 0; kt < KT; ++kt) {
        if (kt == KT - 1) cp_wait<0>(); else cp_wait<1>();
        __syncthreads();
        if (kt + 2 < KT) load_stage((kt + 2) % 3, kt + 2);

        const uint32_t st = sbase + (kt % 3) * GSTAGE;
        const uint32_t aBase = st + aRowOff;
        const uint32_t bBase = st + bRowOff;

        LOAD_FRAGS(0, aBase, bBase, 0);

        #pragma unroll
        for (int ks = 0; ks < 4; ++ks) {
            const int cur = ks & 1;
            if (ks < 3) {
                const int nxt = cur ^ 1;
                if ((ks & 1) == 0) LOAD_FRAGS(1, aBase, bBase, ks + 1);
                else               LOAD_FRAGS(0, aBase, bBase, ks + 1);
                (void)nxt;
            }
            #pragma unroll
            for (int i = 0; i < 4; ++i)
                #pragma unroll
                for (int j = 0; j < 8; ++j)
                    MMA_BF16(acc[i][j], afr[cur][i], bfr[cur][j]);
        }
    }
    #undef LOAD_FRAGS

    // epilogue
    const float sa = fmaxf(__uint_as_float(g_amax[saslot]), 1e-8f) / 127.f;
    const float sb = fmaxf(__uint_as_float(g_amax[sbslot]), 1e-8f) / 127.f;
    const float s  = sa * sb;

    float lmax = 0.f;
    #pragma unroll
    for (int i = 0; i < 4; ++i) {
        #pragma unroll
        for (int j = 0; j < 8; ++j) {
            const int row0 = rowA0 + wm + i * 16 + (lane >> 2);
            const int col0 = colB0 + wn + j * 8 + (lane & 3) * 2;
            #pragma unroll
            for (int rr = 0; rr < 2; ++rr) {
                const int row = row0 + rr * 8;
                float t0 = fmaf(acc[i][j][rr * 2 + 0], s, bias[col0 + 0]);
                float t1 = fmaf(acc[i][j][rr * 2 + 1], s, bias[col0 + 1]);
                if (EPI == 0) {
                    t0 = 0.5f * t0 * (1.f + erff(t0 * 0.70710678118654752f));
                    t1 = 0.5f * t1 * (1.f + erff(t1 * 0.70710678118654752f));
                    lmax = fmaxf(lmax, fmaxf(fabsf(t0), fabsf(t1)));
                }
                float2 v; v.x = t0; v.y = t1;
                *(float2*)(Cout + (size_t)row * N + col0) = v;
            }
        }
    }
    if (EPI == 0) {
        #pragma unroll
        for (int o = 16; o > 0; o >>= 1)
            lmax = fmaxf(lmax, __shfl_xor_sync(0xffffffffu, lmax, o));
        if (lane == 0) atomicMax(&g_amax[3], __float_as_uint(lmax));
    }
}

#define GEMM_SMEM (3 * GSTAGE)   // 98304 B

// ---------------- launch ----------------------------------------------------
extern "C" void kernel_launch(void* const* d_in, const int* in_sizes, int n_in,
                              void* d_out, int out_size) {
    const float* x  = (const float*)d_in[0];
    const float* w1 = (const float*)d_in[1];
    const float* b1 = (const float*)d_in[2];
    const float* w2 = (const float*)d_in[3];
    const float* b2 = (const float*)d_in[4];
    float* out = (float*)d_out;

    __nv_bfloat16 *xb, *w1b, *w2b, *hb;
    float* hbuf;
    cudaGetSymbolAddress((void**)&xb,   g_xb);
    cudaGetSymbolAddress((void**)&w1b,  g_w1b);
    cudaGetSymbolAddress((void**)&w2b,  g_w2b);
    cudaGetSymbolAddress((void**)&hbuf, g_h);
    cudaGetSymbolAddress((void**)&hb,   g_hb);

    cudaFuncSetAttribute(gemm_bf16_kernel<0>,
                         cudaFuncAttributeMaxDynamicSharedMemorySize, GEMM_SMEM);
    cudaFuncSetAttribute(gemm_bf16_kernel<1>,
                         cudaFuncAttributeMaxDynamicSharedMemorySize, GEMM_SMEM);

    init_kernel<<<1, 32>>>();
    absmax_all_kernel<<<1536, 256>>>((const float4*)x, (const float4*)w1,
                                     (const float4*)w2);
    quant_all_kernel<<<24576, 256>>>((const float4*)x, (const float4*)w1,
                                     (const float4*)w2);
    {
        dim3 grid(H_DIM / 128, M_TOK / 128);
        gemm_bf16_kernel<0><<<grid, 128, GEMM_SMEM>>>(xb, w1b, b1, hbuf,
                                                      D_DIM, H_DIM, 0, 1);
    }
    {
        size_t n4 = ((size_t)M_TOK * H_DIM) / 4;
        quant_h_kernel<<<(unsigned)(n4 / 256), 256>>>((const float4*)hbuf,
                                                      (ushort4*)hb, (int)n4);
    }
    {
        dim3 grid(D_DIM / 128, M_TOK / 128);
        gemm_bf16_kernel<1><<<grid, 128, GEMM_SMEM>>>(hb, w2b, b2, out,
                                                      H_DIM, D_DIM, 3, 2);
    }
    (void)in_sizes; (void)n_in; (void)out_size;
}